// round 14
// baseline (speedup 1.0000x reference)
#include <cuda_runtime.h>
#include <math.h>

#define BATCH  2
#define KPATCH 1600
#define DDIM   1024
#define CCLS   256
#define NBOX   32
#define PGRID  40
#define BN     (BATCH*NBOX)            /* 64 */
#define NK     (BATCH*KPATCH)          /* 3200 patch rows */
#define NORMB  432                     /* (3200+256)/8 rows-per-block */
#define PREPB  (NORMB + BN)            /* 496 */
#define DCH    8                       /* d-chunks of 128 */
#define KSL    32                      /* k-slices of 100 */

// ---------------- scratch (static device globals; no allocation) ----------------
__device__ float g_fninv[NK];              // 1/||feats[k,:]||
__device__ float g_eninv[CCLS];            // 1/||emb[c,:]||
__device__ float g_cntinv[BN];             // 1/(box pixel count)
__device__ float g_W[NK*NBOX];             // per-patch box weights vy*vx (1.6MB)
__device__ float g_Q[BN*DDIM];             // reduced weighted feature sums

// Keys cubic, a = -0.5 (matches jax.image.resize 'bicubic')
__device__ __forceinline__ float cubicf(float x) {   // x >= 0
    if (x < 1.f) return ((1.5f*x - 2.5f)*x)*x + 1.f;
    if (x < 2.f) return ((-0.5f*x + 2.5f)*x - 4.f)*x + 2.f;
    return 0.f;
}

// ---------------- kernel 1: norms + W matrix + zeroing --------------------------
__global__ void __launch_bounds__(256) prep_kernel(
        const float* __restrict__ feats,
        const float* __restrict__ emb,
        const int* __restrict__ boxes,
        float* __restrict__ out) {
    int blk  = blockIdx.x;
    int t    = threadIdx.x;
    int warp = t >> 5, lane = t & 31;

    if (blk < NORMB) {
        // ---- norm branch: warp-per-row, MLP=8; rows 0..3455 -------------------
        int row = blk * 8 + warp;
        const float4* p4 = (row < NK)
                 ? (const float4*)(feats + (size_t)row * DDIM)
                 : (const float4*)(emb   + (size_t)(row - NK) * DDIM);
        float4 v[8];
        #pragma unroll
        for (int i = 0; i < 8; ++i) v[i] = p4[lane + 32*i];
        float ss = 0.f;
        #pragma unroll
        for (int i = 0; i < 8; ++i)
            ss += v[i].x*v[i].x + v[i].y*v[i].y + v[i].z*v[i].z + v[i].w*v[i].w;
        #pragma unroll
        for (int o = 16; o; o >>= 1) ss += __shfl_xor_sync(0xffffffffu, ss, o);
        if (lane == 0) {
            float inv = 1.0f / sqrtf(ss);
            if (row < NK) g_fninv[row] = inv;
            else          g_eninv[row - NK] = inv;
        }
        if (blk < 256) g_Q[blk * 256 + t] = 0.f;   // zero g_Q (65536 floats)
    } else {
        // ---- box branch: build W column + cntinv + zero out slice -------------
        int bn = blk - NORMB;
        int b = bn >> 5, n = bn & 31;
        int x_min = boxes[bn*4+0], y_min = boxes[bn*4+1];
        int x_max = boxes[bn*4+2], y_max = boxes[bn*4+3];

        __shared__ float sv[2*PGRID];
        if (t < 2*PGRID) sv[t] = 0.f;
        __syncthreads();

        // zero this box's W column (its image's 1600 rows)
        for (int k = t; k < KPATCH; k += 256)
            g_W[(size_t)(b*KPATCH + k) * NBOX + n] = 0.f;

        // pixel-parallel bicubic tap weight accumulation
        int ny = y_max - 1 - y_min;
        int nx = x_max - 1 - x_min;
        for (int i = t; i < ny + nx; i += 256) {
            int y; float* dst;
            if (i < ny) { y = y_min + i;        dst = sv; }
            else        { y = x_min + (i - ny); dst = sv + PGRID; }
            float sf = (y + 0.5f) * (1.0f/14.0f) - 0.5f;
            int i0 = (int)floorf(sf);
            float w[4]; float cs = 0.f;
            #pragma unroll
            for (int j = 0; j < 4; ++j) {
                int ii = i0 - 1 + j;
                float c = (ii >= 0 && ii < PGRID) ? cubicf(fabsf(sf - (float)ii)) : 0.f;
                w[j] = c; cs += c;
            }
            float inv = __fdividef(1.0f, cs);
            #pragma unroll
            for (int j = 0; j < 4; ++j) {
                int ii = i0 - 1 + j;
                if (ii >= 0 && ii < PGRID && w[j] != 0.f)
                    atomicAdd(&dst[ii], w[j] * inv);
            }
        }
        out[bn * CCLS + t] = 0.f;                  // zero output slice
        if (t == 0) g_cntinv[bn] = __fdividef(1.0f, (float)(ny * nx));
        __syncthreads();

        // tap rectangle; write nonzero weights into W column
        float sfl = (y_min + 0.5f) * (1.0f/14.0f) - 0.5f;
        float sfh = (y_max - 2 + 0.5f) * (1.0f/14.0f) - 0.5f;
        int p0 = max(0, (int)floorf(sfl) - 1);
        int p1 = min(PGRID - 1, (int)floorf(sfh) + 2);
        sfl = (x_min + 0.5f) * (1.0f/14.0f) - 0.5f;
        sfh = (x_max - 2 + 0.5f) * (1.0f/14.0f) - 0.5f;
        int q0 = max(0, (int)floorf(sfl) - 1);
        int q1 = min(PGRID - 1, (int)floorf(sfh) + 2);
        int nq = q1 - q0 + 1;
        int ntaps = (p1 - p0 + 1) * nq;            // <= 225

        if (t < ntaps) {
            int pi = t / nq;
            int qi = t - pi * nq;
            int p = p0 + pi, q = q0 + qi;
            g_W[(size_t)(b*KPATCH + p*PGRID + q) * NBOX + n] = sv[p] * sv[PGRID + q];
        }
    }
    __threadfence();
    cudaTriggerProgrammaticLaunchCompletion();
}

// ---------------- kernel 2: patch-centric scatter (PDL secondary) ---------------
// grid (DCH, KSL). Block = (d-chunk of 128, slice of 100 patches).
// Per patch: warp loads W row (32 floats, coalesced) + 4 feats values/lane,
// ballots nonzero boxes (~3), accumulates into smem Qacc[32][128], then REDGs
// the block's Qacc into g_Q.
__global__ void __launch_bounds__(256, 4) scatter_kernel(
        const float* __restrict__ feats) {
    __shared__ float Qacc[NBOX * 128];             // 16KB
    int dch   = blockIdx.x;
    int slice = blockIdx.y;
    int t     = threadIdx.x;
    int warp  = t >> 5, lane = t & 31;

    #pragma unroll
    for (int i = 0; i < 16; ++i) Qacc[i * 256 + t] = 0.f;

    cudaGridDependencySynchronize();               // wait for prep
    __syncthreads();

    int k0 = slice * 100;
    int b  = slice >> 4;                           // 16 slices per image
    int dbase = dch * 128;

    for (int kk = k0 + warp; kk < k0 + 100; kk += 8) {
        float wrow = g_W[(size_t)kk * NBOX + lane];           // coalesced 128B
        float fn   = g_fninv[kk];                             // broadcast
        const float* frow = feats + (size_t)kk * DDIM + dbase;
        float v0 = frow[lane];
        float v1 = frow[lane + 32];
        float v2 = frow[lane + 64];
        float v3 = frow[lane + 96];
        unsigned mask = __ballot_sync(0xffffffffu, wrow != 0.f);
        while (mask) {
            int n = __ffs(mask) - 1;
            mask &= mask - 1;
            float wf = __shfl_sync(0xffffffffu, wrow, n) * fn;
            float* qa = &Qacc[n * 128 + lane];
            atomicAdd(qa +  0, wf * v0);
            atomicAdd(qa + 32, wf * v1);
            atomicAdd(qa + 64, wf * v2);
            atomicAdd(qa + 96, wf * v3);
        }
    }
    __syncthreads();

    // reduce block's Qacc into global Q (boxes of image b)
    #pragma unroll
    for (int i = 0; i < 16; ++i) {
        int f = t + 256 * i;
        int n = f >> 7, d = f & 127;
        atomicAdd(&g_Q[(size_t)(b*NBOX + n) * DDIM + dbase + d], Qacc[f]);
    }
    __threadfence();
    cudaTriggerProgrammaticLaunchCompletion();
}

// ---------------- kernel 3: out += (Q @ embT) * eninv * cntinv (PDL secondary) --
__global__ void __launch_bounds__(256) out_kernel(const float* __restrict__ emb,
                                                  float* __restrict__ out) {
    __shared__ float Qs[16 * 64];      // [bn][dd]  4KB
    __shared__ float Es[32 * 68];      // [c][dd]   8.5KB, stride 68 (raw emb)
    int c0  = blockIdx.x * 32;
    int d0  = blockIdx.y * 64;
    int bn0 = blockIdx.z * 16;
    int t   = threadIdx.x;

    // independent prologue: raw E tile
    const float4* e4 = (const float4*)emb;
    #pragma unroll
    for (int i = 0; i < 2; ++i) {
        int lin = i * 256 + t;
        int c = lin >> 4, dd4 = lin & 15;
        float4 a = e4[(size_t)(c0 + c) * 256 + (d0>>2) + dd4];
        *(float4*)&Es[c*68 + dd4*4] = a;
    }

    cudaGridDependencySynchronize();   // wait for scatter

    {   // Q tile: one float4 per thread from the reduced g_Q
        int bn = t >> 4, dd4 = t & 15;
        float4 v = ((const float4*)g_Q)[(size_t)(bn0 + bn) * 256 + (d0>>2) + dd4];
        ((float4*)Qs)[bn*16 + dd4] = v;
    }
    __syncthreads();

    int c = t & 31, g = t >> 5;        // 8 groups x 2 bn each
    float acc[2] = {0.f, 0.f};
    #pragma unroll
    for (int dd4 = 0; dd4 < 16; ++dd4) {
        float4 e = *(const float4*)&Es[c*68 + dd4*4];
        #pragma unroll
        for (int j = 0; j < 2; ++j) {
            float4 q = ((const float4*)Qs)[(g*2 + j)*16 + dd4];   // broadcast
            acc[j] += q.x*e.x + q.y*e.y + q.z*e.z + q.w*e.w;
        }
    }
    float en = g_eninv[c0 + c];
    #pragma unroll
    for (int j = 0; j < 2; ++j) {
        int bn = bn0 + g*2 + j;
        atomicAdd(&out[bn*CCLS + c0 + c], acc[j] * en * g_cntinv[bn]);
    }
}

// ---------------- launch --------------------------------------------------------
extern "C" void kernel_launch(void* const* d_in, const int* in_sizes, int n_in,
                              void* d_out, int out_size) {
    (void)in_sizes; (void)n_in; (void)out_size;
    const float* feats = (const float*)d_in[0];
    const float* emb   = (const float*)d_in[1];
    const int*   boxes = (const int*)d_in[2];
    float* out = (float*)d_out;

    prep_kernel<<<PREPB, 256>>>(feats, emb, boxes, out);

    cudaLaunchAttribute attrs[1];
    attrs[0].id = cudaLaunchAttributeProgrammaticStreamSerialization;
    attrs[0].val.programmaticStreamSerializationAllowed = 1;

    cudaLaunchConfig_t cfg1 = {};
    cfg1.gridDim  = dim3(DCH, KSL);
    cfg1.blockDim = dim3(256, 1, 1);
    cfg1.stream   = 0;
    cfg1.attrs    = attrs;
    cfg1.numAttrs = 1;
    cudaLaunchKernelEx(&cfg1, scatter_kernel, feats);

    cudaLaunchConfig_t cfg2 = {};
    cfg2.gridDim  = dim3(CCLS/32, DDIM/64, BN/16);
    cfg2.blockDim = dim3(256, 1, 1);
    cfg2.stream   = 0;
    cfg2.attrs    = attrs;
    cfg2.numAttrs = 1;
    cudaLaunchKernelEx(&cfg2, out_kernel, emb, out);
}

// round 15
// speedup vs baseline: 1.5913x; 1.5913x over previous
#include <cuda_runtime.h>
#include <math.h>

#define BATCH  2
#define KPATCH 1600
#define DDIM   1024
#define CCLS   256
#define NBOX   32
#define PGRID  40
#define BN     (BATCH*NBOX)            /* 64 */
#define NK     (BATCH*KPATCH)          /* 3200 */
#define NROWS  (NK + CCLS)             /* 3456 norm rows */
#define NORMB  (NROWS/8)               /* 432 */
#define PREPB  (NORMB + BN)            /* 496 */
#define QSPLIT 6
#define NSLOTS (QSPLIT*8)              /* 48 warp-slots per box */

// ---------------- scratch (static device globals; no allocation) ----------------
__device__ float g_fninv[NK];              // 1/||feats[k,:]||
__device__ float g_eninv[CCLS];            // 1/||emb[c,:]||
__device__ float g_vy[BN*PGRID];           // per-box summed weights (y)
__device__ float g_vx[BN*PGRID];           // per-box summed weights (x)
__device__ int   g_rect[BN*4];             // p0,p1,q0,q1
__device__ float g_cntinv[BN];             // 1/(box pixel count)
__device__ float g_Qpart[QSPLIT*BN*DDIM];  // partial weighted feature sums

// Keys cubic, a = -0.5 (matches jax.image.resize 'bicubic')
__device__ __forceinline__ float cubicf(float x) {   // x >= 0
    if (x < 1.f) return ((1.5f*x - 2.5f)*x)*x + 1.f;
    if (x < 2.f) return ((-0.5f*x + 2.5f)*x - 4.f)*x + 2.f;
    return 0.f;
}

// ---------------- kernel 1: norms + box tap vectors + zero out ------------------
__global__ void __launch_bounds__(256) prep_kernel(
        const float* __restrict__ feats,
        const float* __restrict__ emb,
        const int* __restrict__ boxes,
        float* __restrict__ out) {
    int blk  = blockIdx.x;
    int t    = threadIdx.x;
    int warp = t >> 5, lane = t & 31;

    if (blk < NORMB) {
        // ---- norm branch: warp-per-row, MLP=8 ---------------------------------
        int row = blk * 8 + warp;
        const float4* p4 = (row < NK)
                 ? (const float4*)(feats + (size_t)row * DDIM)
                 : (const float4*)(emb   + (size_t)(row - NK) * DDIM);
        float4 v[8];
        #pragma unroll
        for (int i = 0; i < 8; ++i) v[i] = p4[lane + 32*i];
        float ss = 0.f;
        #pragma unroll
        for (int i = 0; i < 8; ++i)
            ss += v[i].x*v[i].x + v[i].y*v[i].y + v[i].z*v[i].z + v[i].w*v[i].w;
        #pragma unroll
        for (int o = 16; o; o >>= 1) ss += __shfl_xor_sync(0xffffffffu, ss, o);
        if (lane == 0) {
            float inv = 1.0f / sqrtf(ss);
            if (row < NK) g_fninv[row] = inv;
            else          g_eninv[row - NK] = inv;
        }
    } else {
        // ---- box branch: per-pixel-parallel bicubic tap weights ----------------
        int bn = blk - NORMB;
        int x_min = boxes[bn*4+0], y_min = boxes[bn*4+1];
        int x_max = boxes[bn*4+2], y_max = boxes[bn*4+3];

        __shared__ float sv[2*PGRID];
        if (t < 2*PGRID) sv[t] = 0.f;
        __syncthreads();

        int ny = y_max - 1 - y_min;
        int nx = x_max - 1 - x_min;
        for (int i = t; i < ny + nx; i += 256) {
            int y; float* dst;
            if (i < ny) { y = y_min + i;        dst = sv; }
            else        { y = x_min + (i - ny); dst = sv + PGRID; }
            float sf = (y + 0.5f) * (1.0f/14.0f) - 0.5f;
            int i0 = (int)floorf(sf);
            float w[4]; float cs = 0.f;
            #pragma unroll
            for (int j = 0; j < 4; ++j) {
                int ii = i0 - 1 + j;
                float c = (ii >= 0 && ii < PGRID) ? cubicf(fabsf(sf - (float)ii)) : 0.f;
                w[j] = c; cs += c;
            }
            float inv = __fdividef(1.0f, cs);
            #pragma unroll
            for (int j = 0; j < 4; ++j) {
                int ii = i0 - 1 + j;
                if (ii >= 0 && ii < PGRID && w[j] != 0.f)
                    atomicAdd(&dst[ii], w[j] * inv);
            }
        }
        out[bn * CCLS + t] = 0.f;                  // zero output slice
        __syncthreads();
        if (t < PGRID)        g_vy[bn*PGRID + t]           = sv[t];
        else if (t < 2*PGRID) g_vx[bn*PGRID + (t - PGRID)] = sv[t];
        if (t == 0) {
            float sfl = (y_min + 0.5f) * (1.0f/14.0f) - 0.5f;
            float sfh = (y_max - 2 + 0.5f) * (1.0f/14.0f) - 0.5f;
            int p0 = max(0, (int)floorf(sfl) - 1);
            int p1 = min(PGRID - 1, (int)floorf(sfh) + 2);
            sfl = (x_min + 0.5f) * (1.0f/14.0f) - 0.5f;
            sfh = (x_max - 2 + 0.5f) * (1.0f/14.0f) - 0.5f;
            int q0 = max(0, (int)floorf(sfl) - 1);
            int q1 = min(PGRID - 1, (int)floorf(sfh) + 2);
            g_rect[bn*4+0] = p0; g_rect[bn*4+1] = p1;
            g_rect[bn*4+2] = q0; g_rect[bn*4+3] = q1;
            g_cntinv[bn] = __fdividef(1.0f, (float)(ny * nx));
        }
    }
}

// ---------------- kernel 2: Q partials — pure load+FMA tap stream ---------------
// grid (QSPLIT, BN). Tap list folds vy*vx*fninv at setup; the mainloop has no
// cross-lane ops at all: 8 independent LDG.128 + 32 FFMA per tap, fully
// pipelined across taps and warps.
__global__ void __launch_bounds__(256, 3) q_kernel(const float* __restrict__ feats) {
    int s    = blockIdx.x;
    int bn   = blockIdx.y;
    int t    = threadIdx.x;
    int warp = t >> 5, lane = t & 31;
    int b    = bn >> 5;

    __shared__ int   rect[4];
    __shared__ unsigned short taps[256];       // k index per tap
    __shared__ float wt[256];                  // vy*vx*fninv per tap
    __shared__ float red[8*DDIM];              // per-warp partials (32KB)

    if (t < 4) rect[t] = g_rect[bn*4+t];
    __syncthreads();
    int p0 = rect[0], p1 = rect[1], q0 = rect[2], q1 = rect[3];
    int nq = q1 - q0 + 1;
    int ntaps = (p1 - p0 + 1) * nq;            // <= 225

    if (t < ntaps) {
        int pi = t / nq;
        int qi = t - pi * nq;
        int p = p0 + pi, q = q0 + qi;
        int k = p * PGRID + q;
        taps[t] = (unsigned short)k;
        wt[t]   = g_vy[bn*PGRID + p] * g_vx[bn*PGRID + q] * g_fninv[b*KPATCH + k];
    }
    __syncthreads();

    // ---- warp-slot tap stream: no reduce, no rsqrt ----------------------------
    int slot = s * 8 + warp;                   // 0..47
    float4 acc[8];
    #pragma unroll
    for (int i = 0; i < 8; ++i) acc[i] = make_float4(0.f,0.f,0.f,0.f);

    const float4* f4 = (const float4*)feats + (size_t)b * KPATCH * 256;
    for (int it = slot; it < ntaps; it += NSLOTS) {
        const float4* r = f4 + (size_t)taps[it] * 256;
        float w = wt[it];
        float4 v[8];
        #pragma unroll
        for (int i = 0; i < 8; ++i) v[i] = r[lane + 32*i];     // MLP=8
        #pragma unroll
        for (int i = 0; i < 8; ++i) {
            acc[i].x += w * v[i].x; acc[i].y += w * v[i].y;
            acc[i].z += w * v[i].z; acc[i].w += w * v[i].w;
        }
    }

    // ---- block reduce over 8 warps --------------------------------------------
    #pragma unroll
    for (int i = 0; i < 8; ++i)
        ((float4*)red)[warp*256 + lane + 32*i] = acc[i];
    __syncthreads();
    float4 sum = make_float4(0.f,0.f,0.f,0.f);
    #pragma unroll
    for (int w = 0; w < 8; ++w) {
        float4 a = ((const float4*)red)[w*256 + t];
        sum.x += a.x; sum.y += a.y; sum.z += a.z; sum.w += a.w;
    }
    ((float4*)g_Qpart)[(size_t)(s*BN + bn) * 256 + t] = sum;
}

// ---------------- kernel 3: out += (Q @ embT) * cntinv  (bn-split, 512 blocks) --
__global__ void __launch_bounds__(256) out_kernel(const float* __restrict__ emb,
                                                  float* __restrict__ out) {
    __shared__ float Qs[16 * 64];      // [bn][dd]  4KB
    __shared__ float Es[32 * 68];      // [c][dd]   8.5KB, stride 68
    int c0  = blockIdx.x * 32;
    int d0  = blockIdx.y * 64;
    int bn0 = blockIdx.z * 16;
    int t   = threadIdx.x;

    {   // Q tile: 256 float4 (16 bn x 16 dd4), sum QSPLIT partials
        int bn = t >> 4, dd4 = t & 15;
        const float4* qp4 = (const float4*)g_Qpart;
        float4 v = make_float4(0.f,0.f,0.f,0.f);
        #pragma unroll
        for (int sp = 0; sp < QSPLIT; ++sp) {
            float4 a = qp4[(size_t)(sp*BN + bn0 + bn) * 256 + (d0>>2) + dd4];
            v.x += a.x; v.y += a.y; v.z += a.z; v.w += a.w;
        }
        ((float4*)Qs)[bn*16 + dd4] = v;
    }
    const float4* e4 = (const float4*)emb;
    #pragma unroll
    for (int i = 0; i < 2; ++i) {
        int lin = i * 256 + t;             // 0..511
        int c = lin >> 4, dd4 = lin & 15;
        float sc = g_eninv[c0 + c];
        float4 a = e4[(size_t)(c0 + c) * 256 + (d0>>2) + dd4];
        a.x *= sc; a.y *= sc; a.z *= sc; a.w *= sc;
        *(float4*)&Es[c*68 + dd4*4] = a;
    }
    __syncthreads();

    int c = t & 31, g = t >> 5;            // 8 groups x 2 bn each
    float acc[2] = {0.f, 0.f};
    #pragma unroll
    for (int dd4 = 0; dd4 < 16; ++dd4) {
        float4 e = *(const float4*)&Es[c*68 + dd4*4];
        #pragma unroll
        for (int j = 0; j < 2; ++j) {
            float4 q = ((const float4*)Qs)[(g*2 + j)*16 + dd4];   // broadcast
            acc[j] += q.x*e.x + q.y*e.y + q.z*e.z + q.w*e.w;
        }
    }
    #pragma unroll
    for (int j = 0; j < 2; ++j) {
        int bn = bn0 + g*2 + j;
        atomicAdd(&out[bn*CCLS + c0 + c], acc[j] * g_cntinv[bn]);
    }
}

// ---------------- launch --------------------------------------------------------
extern "C" void kernel_launch(void* const* d_in, const int* in_sizes, int n_in,
                              void* d_out, int out_size) {
    (void)in_sizes; (void)n_in; (void)out_size;
    const float* feats = (const float*)d_in[0];
    const float* emb   = (const float*)d_in[1];
    const int*   boxes = (const int*)d_in[2];
    float* out = (float*)d_out;

    prep_kernel<<<PREPB, 256>>>(feats, emb, boxes, out);
    q_kernel<<<dim3(QSPLIT, BN), 256>>>(feats);
    out_kernel<<<dim3(CCLS/32, DDIM/64, BN/16), 256>>>(emb, out);
}

// round 17
// speedup vs baseline: 1.9630x; 1.2336x over previous
#include <cuda_runtime.h>
#include <math.h>

#define BATCH  2
#define KPATCH 1600
#define DDIM   1024
#define CCLS   256
#define NBOX   32
#define PGRID  40
#define BN     (BATCH*NBOX)            /* 64 */
#define QSPLIT 6
#define NSLOTS (QSPLIT*8)              /* 48 warp-slots per box */

// ---------------- scratch (static device globals; no allocation) ----------------
__device__ float g_eninv[CCLS];
__device__ float g_cntinv[BN];
__device__ float g_Qpart[QSPLIT*BN*DDIM];

// Keys cubic, a = -0.5 (matches jax.image.resize 'bicubic')
__device__ __forceinline__ float cubicf(float x) {   // x >= 0
    if (x < 1.f) return ((1.5f*x - 2.5f)*x)*x + 1.f;
    if (x < 2.f) return ((-0.5f*x + 2.5f)*x - 4.f)*x + 2.f;
    return 0.f;
}

// single-MUFU reciprocal sqrt (avoids sqrt.rn + div.rn refinement sequences)
__device__ __forceinline__ float rsqrt_fast(float x) {
    float r;
    asm("rsqrt.approx.f32 %0, %1;" : "=f"(r) : "f"(x));
    return r;
}

// ---------------- kernel 1: Q partials, high-occupancy single-tap loop ----------
// grid (QSPLIT+1, BN). s<QSPLIT: Q work. s==QSPLIT: misc (emb norms + zero out).
__global__ void __launch_bounds__(256, 3) q_kernel(
        const float* __restrict__ feats,
        const float* __restrict__ emb,
        const int* __restrict__ boxes,
        float* __restrict__ out) {
    int s    = blockIdx.x;
    int bn   = blockIdx.y;
    int t    = threadIdx.x;
    int warp = t >> 5, lane = t & 31;

    if (s == QSPLIT) {
        // ---- misc: 4 emb-row norms (2 warps/row, MLP=4) + zero out slice ------
        __shared__ float ws[8];
        int row  = bn * 4 + (warp >> 1);
        int half = warp & 1;
        const float4* p4 = (const float4*)(emb) + (size_t)row * 256 + half * 128;
        float4 v[4];
        #pragma unroll
        for (int i = 0; i < 4; ++i) v[i] = p4[lane + 32*i];
        float ss = 0.f;
        #pragma unroll
        for (int i = 0; i < 4; ++i)
            ss += v[i].x*v[i].x + v[i].y*v[i].y + v[i].z*v[i].z + v[i].w*v[i].w;
        #pragma unroll
        for (int o = 16; o; o >>= 1) ss += __shfl_xor_sync(0xffffffffu, ss, o);
        if (lane == 0) ws[warp] = ss;
        out[bn * CCLS + t] = 0.f;              // zero output (64 blocks x 256)
        __syncthreads();
        if (t < 4) g_eninv[bn*4 + t] = rsqrt_fast(ws[2*t] + ws[2*t+1]);
        return;
    }

    __shared__ float sv[2*PGRID];              // vy[0..39], vx[40..79]
    __shared__ unsigned short taps[256];       // p*40+q per tap
    __shared__ float wt[256];                  // vy[p]*vx[q]
    __shared__ float red[8*DDIM];              // per-warp partials (32KB)

    int x_min = boxes[bn*4+0], y_min = boxes[bn*4+1];
    int x_max = boxes[bn*4+2], y_max = boxes[bn*4+3];
    if (t < 2*PGRID) sv[t] = 0.f;
    __syncthreads();

    // ---- pixel-parallel bicubic tap weight accumulation -----------------------
    int ny = y_max - 1 - y_min;
    int nx = x_max - 1 - x_min;
    for (int i = t; i < ny + nx; i += 256) {
        int y; float* dst;
        if (i < ny) { y = y_min + i;        dst = sv; }
        else        { y = x_min + (i - ny); dst = sv + PGRID; }
        float sf = (y + 0.5f) * (1.0f/14.0f) - 0.5f;
        int i0 = (int)floorf(sf);
        float w[4]; float cs = 0.f;
        #pragma unroll
        for (int j = 0; j < 4; ++j) {
            int ii = i0 - 1 + j;
            float c = (ii >= 0 && ii < PGRID) ? cubicf(fabsf(sf - (float)ii)) : 0.f;
            w[j] = c; cs += c;
        }
        float inv = __fdividef(1.0f, cs);
        #pragma unroll
        for (int j = 0; j < 4; ++j) {
            int ii = i0 - 1 + j;
            if (ii >= 0 && ii < PGRID && w[j] != 0.f)
                atomicAdd(&dst[ii], w[j] * inv);
        }
    }
    if (t == 0 && s == 0)
        g_cntinv[bn] = __fdividef(1.0f, (float)(ny * nx));
    __syncthreads();

    // ---- tap rectangle + tap list (one int-div per thread, setup only) --------
    float sfl = (y_min + 0.5f) * (1.0f/14.0f) - 0.5f;
    float sfh = (y_max - 2 + 0.5f) * (1.0f/14.0f) - 0.5f;
    int p0 = max(0, (int)floorf(sfl) - 1);
    int p1 = min(PGRID - 1, (int)floorf(sfh) + 2);
    sfl = (x_min + 0.5f) * (1.0f/14.0f) - 0.5f;
    sfh = (x_max - 2 + 0.5f) * (1.0f/14.0f) - 0.5f;
    int q0 = max(0, (int)floorf(sfl) - 1);
    int q1 = min(PGRID - 1, (int)floorf(sfh) + 2);
    int nq = q1 - q0 + 1;
    int ntaps = (p1 - p0 + 1) * nq;            // <= 225

    if (t < ntaps) {
        int pi = t / nq;
        int qi = t - pi * nq;
        int p = p0 + pi, q = q0 + qi;
        taps[t] = (unsigned short)(p * PGRID + q);
        wt[t]   = sv[p] * sv[PGRID + q];
    }
    __syncthreads();

    // ---- warp-slot single-tap accumulation with inline norm -------------------
    int slot = s * 8 + warp;                   // 0..47
    int b    = bn >> 5;
    float4 acc[8];
    #pragma unroll
    for (int i = 0; i < 8; ++i) acc[i] = make_float4(0.f,0.f,0.f,0.f);

    const float4* f4 = (const float4*)feats + (size_t)b * KPATCH * 256;
    for (int it = slot; it < ntaps; it += NSLOTS) {
        const float4* r = f4 + (size_t)taps[it] * 256;
        float4 v[8];
        #pragma unroll
        for (int i = 0; i < 8; ++i) v[i] = r[lane + 32*i];     // MLP=8
        float ss = 0.f;
        #pragma unroll
        for (int i = 0; i < 8; ++i)
            ss += v[i].x*v[i].x + v[i].y*v[i].y + v[i].z*v[i].z + v[i].w*v[i].w;
        #pragma unroll
        for (int o = 16; o; o >>= 1) ss += __shfl_xor_sync(0xffffffffu, ss, o);
        float w = wt[it] * rsqrt_fast(ss);      // single MUFU.RSQ, no div chain
        #pragma unroll
        for (int i = 0; i < 8; ++i) {
            acc[i].x += w * v[i].x; acc[i].y += w * v[i].y;
            acc[i].z += w * v[i].z; acc[i].w += w * v[i].w;
        }
    }

    // ---- block reduce over 8 warps --------------------------------------------
    #pragma unroll
    for (int i = 0; i < 8; ++i)
        ((float4*)red)[warp*256 + lane + 32*i] = acc[i];
    __syncthreads();
    float4 sum = make_float4(0.f,0.f,0.f,0.f);
    #pragma unroll
    for (int w = 0; w < 8; ++w) {
        float4 a = ((const float4*)red)[w*256 + t];
        sum.x += a.x; sum.y += a.y; sum.z += a.z; sum.w += a.w;
    }
    ((float4*)g_Qpart)[(size_t)(s*BN + bn) * 256 + t] = sum;
}

// ---------------- kernel 2: out += (Q @ embT) * cntinv  (bn-split, 512 blocks) --
__global__ void __launch_bounds__(256) out_kernel(const float* __restrict__ emb,
                                                  float* __restrict__ out) {
    __shared__ float Qs[16 * 64];      // [bn][dd]  4KB (16-bn slice)
    __shared__ float Es[32 * 68];      // [c][dd]   8.5KB, stride 68
    int c0  = blockIdx.x * 32;
    int d0  = blockIdx.y * 64;
    int bn0 = blockIdx.z * 16;
    int t   = threadIdx.x;

    {   // Q tile: 256 float4 (16 bn x 16 dd4), sum QSPLIT partials
        int bn = t >> 4, dd4 = t & 15;
        const float4* qp4 = (const float4*)g_Qpart;
        float4 v = make_float4(0.f,0.f,0.f,0.f);
        #pragma unroll
        for (int sp = 0; sp < QSPLIT; ++sp) {
            float4 a = qp4[(size_t)(sp*BN + bn0 + bn) * 256 + (d0>>2) + dd4];
            v.x += a.x; v.y += a.y; v.z += a.z; v.w += a.w;
        }
        ((float4*)Qs)[bn*16 + dd4] = v;
    }
    const float4* e4 = (const float4*)emb;
    #pragma unroll
    for (int i = 0; i < 2; ++i) {
        int lin = i * 256 + t;             // 0..511
        int c = lin >> 4, dd4 = lin & 15;
        float sc = g_eninv[c0 + c];
        float4 a = e4[(size_t)(c0 + c) * 256 + (d0>>2) + dd4];
        a.x *= sc; a.y *= sc; a.z *= sc; a.w *= sc;
        *(float4*)&Es[c*68 + dd4*4] = a;
    }
    __syncthreads();

    int c = t & 31, g = t >> 5;            // 8 groups x 2 bn each
    float acc[2] = {0.f, 0.f};
    #pragma unroll
    for (int dd4 = 0; dd4 < 16; ++dd4) {
        float4 e = *(const float4*)&Es[c*68 + dd4*4];
        #pragma unroll
        for (int j = 0; j < 2; ++j) {
            float4 q = ((const float4*)Qs)[(g*2 + j)*16 + dd4];   // broadcast
            acc[j] += q.x*e.x + q.y*e.y + q.z*e.z + q.w*e.w;
        }
    }
    #pragma unroll
    for (int j = 0; j < 2; ++j) {
        int bn = bn0 + g*2 + j;
        atomicAdd(&out[bn*CCLS + c0 + c], acc[j] * g_cntinv[bn]);
    }
}

// ---------------- launch --------------------------------------------------------
extern "C" void kernel_launch(void* const* d_in, const int* in_sizes, int n_in,
                              void* d_out, int out_size) {
    (void)in_sizes; (void)n_in; (void)out_size;
    const float* feats = (const float*)d_in[0];
    const float* emb   = (const float*)d_in[1];
    const int*   boxes = (const int*)d_in[2];
    float* out = (float*)d_out;

    q_kernel<<<dim3(QSPLIT + 1, BN), 256>>>(feats, emb, boxes, out);
    out_kernel<<<dim3(CCLS/32, DDIM/64, BN/16), 256>>>(emb, out);
}